// round 8
// baseline (speedup 1.0000x reference)
#include <cuda_runtime.h>
#include <cstdint>

#define NB 8
#define NT 4096
#define NC 1024      // C_in == C_out
#define NK 3
#define NWELEM (NK*NC*NC)   // 3145728
#define XSTRIDE (NT + 16)   // g_xq row stride in ints (8 guard ints each side)

// ---------------- device scratch (static; no allocations) ----------------
__device__ __align__(16) signed char g_wq[NK*NC*NC];     // [k][ic(32)][o][j(8 ints)] = 32 i-chans/chunk
__device__ __align__(16) int g_xq[NB*256*XSTRIDE];       // [(b*256+ig)][8 + t], guards zeroed
__device__ float g_mu[NB*NT];
__device__ float g_rstd[NB*NT];
__device__ unsigned int g_absmax[NB*NC];                 // float bits, >=0
__device__ double g_beta_acc;

// ---------------- init: zero accumulators + g_xq guard columns ----------------
__global__ void k_init() {
    int idx = blockIdx.x * blockDim.x + threadIdx.x;
    int stride = gridDim.x * blockDim.x;
    for (int i = idx; i < NB*NC; i += stride) g_absmax[i] = 0u;
    for (int i = idx; i < NB*256*16; i += stride) {
        int row = i >> 4, g = i & 15;
        int col = (g < 8) ? g : (NT + g);     // cols 0..7 and NT+8..NT+15
        g_xq[row * XSTRIDE + col] = 0;
    }
    if (idx == 0) g_beta_acc = 0.0;
}

// ---------------- sum |W| ----------------
__global__ void k_wsum(const float* __restrict__ W) {
    int tid = threadIdx.x;
    float s = 0.f;
    for (int i = blockIdx.x * blockDim.x + tid; i < NWELEM; i += gridDim.x * blockDim.x)
        s += fabsf(W[i]);
    #pragma unroll
    for (int off = 16; off; off >>= 1) s += __shfl_xor_sync(0xFFFFFFFFu, s, off);
    __shared__ float rs[8];
    if ((tid & 31) == 0) rs[tid >> 5] = s;
    __syncthreads();
    if (tid == 0) {
        float tot = 0.f;
        #pragma unroll
        for (int w = 0; w < 8; w++) tot += rs[w];
        atomicAdd(&g_beta_acc, (double)tot);
    }
}

// ---------------- quantize weights: W[o][i][k] -> g_wq [k][ic][o][j] packed ----------------
__global__ void k_quantw(const float* __restrict__ W) {
    int idx = blockIdx.x * blockDim.x + threadIdx.x;
    int total = NK * NC * (NC/4);
    if (idx >= total) return;
    float beta = fmaxf((float)(g_beta_acc * (1.0 / (double)NWELEM)), 1e-5f);
    float inv_beta = 1.f / beta;
    int k  = idx / (NC * (NC/4));
    int r  = idx % (NC * (NC/4));
    int o  = r / (NC/4);
    int i4 = r % (NC/4);
    int p = 0;
    #pragma unroll
    for (int j = 0; j < 4; j++) {
        int i = i4*4 + j;
        float ws = W[(o*NC + i)*NK + k] * inv_beta;
        ws = fminf(fmaxf(ws, -1.f), 1.f);
        int q = (int)rintf(ws);
        p |= (q & 0xFF) << (8*j);
    }
    int ic = i4 >> 3, j8 = i4 & 7;                     // ic in 0..31
    ((int*)g_wq)[((k*32 + ic)*NC + o)*8 + j8] = p;
}

// ---------------- layernorm stats per row (b,t) ----------------
__global__ void k_lnstats(const float* __restrict__ x) {
    int row = blockIdx.x;
    int tid = threadIdx.x;
    const float* xr = x + (size_t)row * NC;
    float s = 0.f, s2 = 0.f;
    #pragma unroll
    for (int j = 0; j < 4; j++) {
        float v = xr[tid + j*256];
        s += v; s2 += v*v;
    }
    #pragma unroll
    for (int off = 16; off; off >>= 1) {
        s  += __shfl_xor_sync(0xFFFFFFFFu, s,  off);
        s2 += __shfl_xor_sync(0xFFFFFFFFu, s2, off);
    }
    __shared__ float rs[8], rq[8];
    if ((tid & 31) == 0) { rs[tid >> 5] = s; rq[tid >> 5] = s2; }
    __syncthreads();
    if (tid == 0) {
        float ts = 0.f, tq = 0.f;
        #pragma unroll
        for (int w = 0; w < 8; w++) { ts += rs[w]; tq += rq[w]; }
        float mu  = ts * (1.f/NC);
        float var = fmaxf(tq * (1.f/NC) - mu*mu, 0.f);
        g_mu[row]   = mu;
        g_rstd[row] = rsqrtf(var + 1e-5f);
    }
}

// ---------------- abs-max over T per (b,c) of normalized x ----------------
__global__ void k_absmax(const float* __restrict__ x,
                         const float* __restrict__ gamma,
                         const float* __restrict__ betaln) {
    int c  = blockIdx.x * blockDim.x + threadIdx.x;
    int b  = blockIdx.z;
    int t0 = blockIdx.y * 256;
    float gm = gamma[c], bb = betaln[c];
    const float* xp = x + ((size_t)(b*NT + t0)) * NC + c;
    const float* mup = g_mu   + b*NT + t0;
    const float* rsp = g_rstd + b*NT + t0;
    float m = 0.f;
    #pragma unroll 8
    for (int tt = 0; tt < 256; tt++) {
        float v = xp[(size_t)tt * NC];
        v = (v - mup[tt]) * rsp[tt] * gm + bb;
        m = fmaxf(m, fabsf(v));
    }
    atomicMax(&g_absmax[b*NC + c], __float_as_uint(m));
}

// ---------------- quantize + transpose x -> g_xq packed [b][ig][8+t] ----------------
__global__ void k_quantx(const float* __restrict__ x,
                         const float* __restrict__ gamma,
                         const float* __restrict__ betaln) {
    __shared__ signed char sq[32*36];
    int tid = threadIdx.x;
    int t0 = blockIdx.x * 32, c0 = blockIdx.y * 32, b = blockIdx.z;
    #pragma unroll
    for (int it = 0; it < 4; it++) {
        int l  = it*256 + tid;
        int tt = l >> 5, cc = l & 31;
        int t = t0 + tt, c = c0 + cc;
        int row = b*NT + t;
        float v = x[(size_t)row * NC + c];
        v = (v - g_mu[row]) * g_rstd[row] * gamma[c] + betaln[c];
        float am = fmaxf(__uint_as_float(g_absmax[b*NC + c]), 1e-5f);
        float q = rintf(v * (127.f / am));
        q = fminf(fmaxf(q, -127.f), 127.f);
        sq[cc*36 + tt] = (signed char)(int)q;
    }
    __syncthreads();
    int igl = tid >> 5, tt = tid & 31;
    int b0 = (int)sq[(igl*4+0)*36 + tt] & 0xFF;
    int b1 = (int)sq[(igl*4+1)*36 + tt] & 0xFF;
    int b2 = (int)sq[(igl*4+2)*36 + tt] & 0xFF;
    int b3 = (int)sq[(igl*4+3)*36 + tt] & 0xFF;
    int p = b0 | (b1 << 8) | (b2 << 16) | (b3 << 24);
    g_xq[((b*256) + (c0 >> 2) + igl) * XSTRIDE + 8 + t0 + tt] = p;
}

// ---------------- warp-specialized conv: IMMA(160 cols) + dp4a(96 cols) per CTA ----------------

__device__ __forceinline__ void mma_s8(int& c0, int& c1, int& c2, int& c3,
                                       int a0, int a1, int a2, int a3,
                                       int b0, int b1) {
    asm volatile("mma.sync.aligned.m16n8k32.row.col.s32.s8.s8.s32 "
                 "{%0,%1,%2,%3}, {%4,%5,%6,%7}, {%8,%9}, {%0,%1,%2,%3};"
                 : "+r"(c0), "+r"(c1), "+r"(c2), "+r"(c3)
                 : "r"(a0), "r"(a1), "r"(a2), "r"(a3), "r"(b0), "r"(b1));
}
__device__ __forceinline__ void bulk_g2s(uint32_t dst, const void* src, uint32_t bytes, uint32_t mbar) {
    asm volatile("cp.async.bulk.shared::cta.global.mbarrier::complete_tx::bytes "
                 "[%0], [%1], %2, [%3];"
                 :: "r"(dst), "l"(src), "r"(bytes), "r"(mbar) : "memory");
}
__device__ __forceinline__ void mbar_init(uint32_t mbar, uint32_t count) {
    asm volatile("mbarrier.init.shared.b64 [%0], %1;" :: "r"(mbar), "r"(count) : "memory");
}
__device__ __forceinline__ void mbar_expect_tx(uint32_t mbar, uint32_t bytes) {
    asm volatile("mbarrier.arrive.expect_tx.shared.b64 _, [%0], %1;" :: "r"(mbar), "r"(bytes) : "memory");
}
__device__ __forceinline__ void mbar_wait(uint32_t mbar, uint32_t parity) {
    asm volatile("{\n\t"
                 ".reg .pred P;\n\t"
                 "WL_%=:\n\t"
                 "mbarrier.try_wait.parity.acquire.cta.shared::cta.b64 P, [%0], %1, 0x989680;\n\t"
                 "@P bra WD_%=;\n\t"
                 "bra WL_%=;\n\t"
                 "WD_%=:\n\t"
                 "}" :: "r"(mbar), "r"(parity) : "memory");
}

#define BSTRIDE 280                   // ints per B smem row (280 % 32 == 24, conflict-free)
#define BROWB   1088                  // bytes copied per B row (272 ints: t0-8 .. t0+263)
#define CHUNK_TX (3*4096 + 8*BROWB)   // 20992
#define NIMMA 10                      // IMMA nt tiles per warp (2 x 80 = 160 cols)
#define DPBASE 160                    // first dp4a output col
#define DPW 12                        // dp4a t-cols per lane (96 = 2*4*12)

__global__ void __launch_bounds__(512)
k_conv_ws(float* __restrict__ out) {
    __shared__ __align__(16) int sA[2][3072];      // [buf][(k*128+row)*8 + j]  12KB each
    __shared__ __align__(16) int sB[2][8*BSTRIDE]; // [buf][ig*280 + col], col 0 == t0-8
    __shared__ __align__(8)  unsigned long long s_mbar[2];

    int tid  = threadIdx.x;
    int lane = tid & 31, warp = tid >> 5;
    int t0 = blockIdx.x * 256;
    int o0 = blockIdx.y * 128;
    int b  = blockIdx.z;

    const char* wqb = (const char*)g_wq;
    const int*  xq  = g_xq;

    uint32_t sA0 = (uint32_t)__cvta_generic_to_shared(&sA[0][0]);
    uint32_t sB0 = (uint32_t)__cvta_generic_to_shared(&sB[0][0]);
    uint32_t mb0 = (uint32_t)__cvta_generic_to_shared(&s_mbar[0]);
    uint32_t mb1 = (uint32_t)__cvta_generic_to_shared(&s_mbar[1]);

    if (tid == 0) { mbar_init(mb0, 1); mbar_init(mb1, 1); }
    __syncthreads();

    auto issue = [&](int ic, int buf) {
        uint32_t mb = buf ? mb1 : mb0;
        uint32_t dA = sA0 + buf*12288;
        uint32_t dB = sB0 + buf*(8*BSTRIDE*4);
        mbar_expect_tx(mb, CHUNK_TX);
        #pragma unroll
        for (int k = 0; k < 3; k++) {
            const void* src = wqb + ((size_t)((k*32 + ic)*NC + o0) << 5);
            bulk_g2s(dA + k*4096, src, 4096, mb);
        }
        #pragma unroll
        for (int ig = 0; ig < 8; ig++) {
            const void* src = xq + (size_t)(b*256 + ic*8 + ig) * XSTRIDE + t0;
            bulk_g2s(dB + ig*(BSTRIDE*4), src, BROWB, mb);
        }
    };

    // shared accumulator storage: imma warps [mt][nt(10)][4] = 80; dp4a [s][12] = 48
    int acc[2*NIMMA*4];
    #pragma unroll
    for (int i = 0; i < 2*NIMMA*4; i++) acc[i] = 0;

    int q = lane & 3, r = lane >> 2;
    int wm = warp & 3, wn = warp >> 2;          // imma warps (0..7); wn in {0,1} -> 80 cols each
    int w2m = (warp - 8) & 3, w2n = (warp >= 12) ? 1 : 0;  // dp4a warps (8..15)
    int ubase = w2n*48 + q*DPW;                 // dp4a lane col base within 96-col region

    if (tid == 0) issue(0, 0);

    for (int ic = 0; ic < 32; ic++) {
        int buf = ic & 1;
        if (ic < 31 && tid == 0) issue(ic + 1, buf ^ 1);
        mbar_wait(buf ? mb1 : mb0, (ic >> 1) & 1);

        const int* A = sA[buf];
        const int* B = sB[buf];

        if (warp < 8) {
            // ---- IMMA: cols t0 .. t0+159 ----
            #pragma unroll
            for (int k = 0; k < 3; k++) {
                int a[2][4];
                #pragma unroll
                for (int mt = 0; mt < 2; mt++) {
                    int rb = wm*32 + mt*16;
                    const int* Ak = A + (k << 10);
                    a[mt][0] = Ak[((rb + r)     << 3) + q];
                    a[mt][1] = Ak[((rb + 8 + r) << 3) + q];
                    a[mt][2] = Ak[((rb + r)     << 3) + 4 + q];
                    a[mt][3] = Ak[((rb + 8 + r) << 3) + 4 + q];
                }
                #pragma unroll
                for (int nt = 0; nt < NIMMA; nt++) {
                    int col = wn*80 + nt*8 + r + k + 7;   // sB col 0 == t0-8
                    int b0 = B[q*BSTRIDE + col];
                    int b1 = B[(4 + q)*BSTRIDE + col];
                    #pragma unroll
                    for (int mt = 0; mt < 2; mt++) {
                        int* ac = &acc[(mt*NIMMA + nt)*4];
                        mma_s8(ac[0], ac[1], ac[2], ac[3],
                               a[mt][0], a[mt][1], a[mt][2], a[mt][3], b0, b1);
                    }
                }
            }
        } else {
            // ---- dp4a: cols t0+160 .. t0+255 ----
            #pragma unroll 1
            for (int j = 0; j < 8; j++) {
                int bb[20];
                #pragma unroll
                for (int i = 0; i < 5; i++) {
                    // base col 164+ubase is 16B-aligned (ubase multiple of 4)
                    int4 v = *(const int4*)&B[j*BSTRIDE + 164 + ubase + 4*i];
                    bb[4*i+0] = v.x; bb[4*i+1] = v.y; bb[4*i+2] = v.z; bb[4*i+3] = v.w;
                }
                int a[3][4];
                #pragma unroll
                for (int k = 0; k < 3; k++)
                    #pragma unroll
                    for (int s = 0; s < 4; s++)
                        a[k][s] = A[((k*128 + w2m*32 + s*8 + r) << 3) + j];
                // out t = t0+160+ubase+uu needs sB col = ubase+uu+k+167 -> bb[3+uu+k]
                #pragma unroll
                for (int k = 0; k < 3; k++)
                    #pragma unroll
                    for (int s = 0; s < 4; s++)
                        #pragma unroll
                        for (int uu = 0; uu < DPW; uu++)
                            acc[s*DPW + uu] = __dp4a(a[k][s], bb[3 + uu + k], acc[s*DPW + uu]);
            }
        }
        __syncthreads();
    }

    // ---- epilogue ----
    float beta = fmaxf((float)(g_beta_acc * (1.0 / (double)NWELEM)), 1e-5f);
    if (warp < 8) {
        #pragma unroll
        for (int mt = 0; mt < 2; mt++) {
            int ro = o0 + wm*32 + mt*16 + r;
            float s0 = beta * fmaxf(__uint_as_float(g_absmax[b*NC + ro]),     1e-5f) * (1.f/127.f);
            float s1 = beta * fmaxf(__uint_as_float(g_absmax[b*NC + ro + 8]), 1e-5f) * (1.f/127.f);
            #pragma unroll
            for (int nt = 0; nt < NIMMA; nt++) {
                int t = t0 + wn*80 + nt*8 + q*2;
                float* p0 = out + ((size_t)(b*NT + t)) * NC;
                float* p1 = p0 + NC;
                const int* ac = &acc[(mt*NIMMA + nt)*4];
                p0[ro]     = (float)ac[0] * s0;
                p1[ro]     = (float)ac[1] * s0;
                p0[ro + 8] = (float)ac[2] * s1;
                p1[ro + 8] = (float)ac[3] * s1;
            }
        }
    } else {
        int tb = t0 + DPBASE + ubase;
        #pragma unroll
        for (int s = 0; s < 4; s++) {
            int ro = o0 + w2m*32 + s*8 + r;
            float osc = beta * fmaxf(__uint_as_float(g_absmax[b*NC + ro]), 1e-5f) * (1.f/127.f);
            #pragma unroll
            for (int uu = 0; uu < DPW; uu++) {
                int t = tb + uu;
                out[((size_t)(b*NT + t))*NC + ro] = (float)acc[s*DPW + uu] * osc;
            }
        }
    }
}

// ---------------- launch ----------------
extern "C" void kernel_launch(void* const* d_in, const int* in_sizes, int n_in,
                              void* d_out, int out_size) {
    const float* x      = (const float*)d_in[0];   // [8,4096,1024]
    const float* gamma  = (const float*)d_in[1];   // [1024]
    const float* betaln = (const float*)d_in[2];   // [1024]
    const float* W      = (const float*)d_in[3];   // [1024,1024,3]
    float* out = (float*)d_out;

    k_init<<<64, 256>>>();
    k_wsum<<<1536, 256>>>(W);
    k_quantw<<<(NK*NC*(NC/4) + 255)/256, 256>>>(W);
    k_lnstats<<<NB*NT, 256>>>(x);
    k_absmax<<<dim3(NC/256, 16, NB), 256>>>(x, gamma, betaln);
    k_quantx<<<dim3(NT/32, NC/32, NB), 256>>>(x, gamma, betaln);
    k_conv_ws<<<dim3(NT/256, NC/128, NB), 512>>>(out);
}

// round 10
// speedup vs baseline: 1.1491x; 1.1491x over previous
#include <cuda_runtime.h>
#include <cstdint>

#define NB 8
#define NT 4096
#define NC 1024      // C_in == C_out
#define NK 3
#define NWELEM (NK*NC*NC)   // 3145728
#define XSTRIDE (NT + 16)   // g_xq row stride in ints (8 guard ints each side)

// ---------------- device scratch (static; no allocations) ----------------
__device__ __align__(16) signed char g_wq[NK*NC*NC];     // [k][ic(32)][o][j(8 ints)]
__device__ __align__(16) int g_xq[NB*256*XSTRIDE];       // [(b*256+ig)][8 + t], guards zeroed
__device__ float g_mu[NB*NT];
__device__ float g_rstd[NB*NT];
__device__ unsigned int g_absmax[NB*NC];                 // float bits, >=0
__device__ double g_beta_acc;

// ---------------- init: zero accumulators + g_xq guard columns ----------------
__global__ void k_init() {
    int idx = blockIdx.x * blockDim.x + threadIdx.x;
    int stride = gridDim.x * blockDim.x;
    for (int i = idx; i < NB*NC; i += stride) g_absmax[i] = 0u;
    for (int i = idx; i < NB*256*16; i += stride) {
        int row = i >> 4, g = i & 15;
        int col = (g < 8) ? g : (NT + g);
        g_xq[row * XSTRIDE + col] = 0;
    }
    if (idx == 0) g_beta_acc = 0.0;
}

// ---------------- sum |W| ----------------
__global__ void k_wsum(const float* __restrict__ W) {
    int tid = threadIdx.x;
    float s = 0.f;
    for (int i = blockIdx.x * blockDim.x + tid; i < NWELEM; i += gridDim.x * blockDim.x)
        s += fabsf(W[i]);
    #pragma unroll
    for (int off = 16; off; off >>= 1) s += __shfl_xor_sync(0xFFFFFFFFu, s, off);
    __shared__ float rs[8];
    if ((tid & 31) == 0) rs[tid >> 5] = s;
    __syncthreads();
    if (tid == 0) {
        float tot = 0.f;
        #pragma unroll
        for (int w = 0; w < 8; w++) tot += rs[w];
        atomicAdd(&g_beta_acc, (double)tot);
    }
}

// ---------------- quantize weights: W[o][i][k] -> g_wq [k][ic][o][j] packed ----------------
__global__ void k_quantw(const float* __restrict__ W) {
    int idx = blockIdx.x * blockDim.x + threadIdx.x;
    int total = NK * NC * (NC/4);
    if (idx >= total) return;
    float beta = fmaxf((float)(g_beta_acc * (1.0 / (double)NWELEM)), 1e-5f);
    float inv_beta = 1.f / beta;
    int k  = idx / (NC * (NC/4));
    int r  = idx % (NC * (NC/4));
    int o  = r / (NC/4);
    int i4 = r % (NC/4);
    int p = 0;
    #pragma unroll
    for (int j = 0; j < 4; j++) {
        int i = i4*4 + j;
        float ws = W[(o*NC + i)*NK + k] * inv_beta;
        ws = fminf(fmaxf(ws, -1.f), 1.f);
        int q = (int)rintf(ws);
        p |= (q & 0xFF) << (8*j);
    }
    int ic = i4 >> 3, j8 = i4 & 7;
    ((int*)g_wq)[((k*32 + ic)*NC + o)*8 + j8] = p;
}

// ---------------- fused LN stats + channel abs-max (one DRAM pass over x) ----------------
__global__ void __launch_bounds__(256)
k_stats(const float* __restrict__ x,
        const float* __restrict__ gamma,
        const float* __restrict__ betaln) {
    __shared__ float s_mu[32], s_rs[32];
    __shared__ unsigned int s_max[NC];
    int tid = threadIdx.x;
    int lane = tid & 31, warp = tid >> 5;
    int b = blockIdx.y;
    int tbase = blockIdx.x * 32;

    #pragma unroll
    for (int h = 0; h < 4; h++) s_max[tid + h*256] = 0u;

    // phase 1: row stats for 4 rows per warp
    #pragma unroll 1
    for (int j = 0; j < 4; j++) {
        int rr = warp*4 + j;
        const float* xr = x + ((size_t)(b*NT + tbase + rr)) * NC;
        float s = 0.f, s2 = 0.f;
        #pragma unroll 8
        for (int m = 0; m < 32; m++) {
            float v = xr[lane + 32*m];
            s += v; s2 += v*v;
        }
        #pragma unroll
        for (int off = 16; off; off >>= 1) {
            s  += __shfl_xor_sync(0xFFFFFFFFu, s,  off);
            s2 += __shfl_xor_sync(0xFFFFFFFFu, s2, off);
        }
        if (lane == 0) {
            float mu  = s * (1.f/NC);
            float var = fmaxf(s2 * (1.f/NC) - mu*mu, 0.f);
            float rstd = rsqrtf(var + 1e-5f);
            s_mu[rr] = mu; s_rs[rr] = rstd;
            g_mu[b*NT + tbase + rr]   = mu;
            g_rstd[b*NT + tbase + rr] = rstd;
        }
    }
    __syncthreads();

    // phase 2: re-read (L1/L2-hot), per-channel abs-max of normalized value
    float mu0 = s_mu[warp*4+0], rs0 = s_rs[warp*4+0];
    float mu1 = s_mu[warp*4+1], rs1 = s_rs[warp*4+1];
    float mu2 = s_mu[warp*4+2], rs2 = s_rs[warp*4+2];
    float mu3 = s_mu[warp*4+3], rs3 = s_rs[warp*4+3];
    const float* xw = x + ((size_t)(b*NT + tbase + warp*4)) * NC;
    #pragma unroll 1
    for (int m = 0; m < 32; m++) {
        int c = lane + 32*m;
        float gm = gamma[c], bb = betaln[c];
        float v0 = fabsf((xw[c]        - mu0) * rs0 * gm + bb);
        float v1 = fabsf((xw[NC + c]   - mu1) * rs1 * gm + bb);
        float v2 = fabsf((xw[2*NC + c] - mu2) * rs2 * gm + bb);
        float v3 = fabsf((xw[3*NC + c] - mu3) * rs3 * gm + bb);
        float mx = fmaxf(fmaxf(v0, v1), fmaxf(v2, v3));
        atomicMax(&s_max[c], __float_as_uint(mx));
    }
    __syncthreads();

    // phase 3: one global atomic per channel
    #pragma unroll
    for (int h = 0; h < 4; h++) {
        int c = tid + h*256;
        atomicMax(&g_absmax[b*NC + c], s_max[c]);
    }
}

// ---------------- quantize + transpose x -> g_xq packed [b][ig][8+t] ----------------
__global__ void k_quantx(const float* __restrict__ x,
                         const float* __restrict__ gamma,
                         const float* __restrict__ betaln) {
    __shared__ signed char sq[32*36];
    int tid = threadIdx.x;
    int t0 = blockIdx.x * 32, c0 = blockIdx.y * 32, b = blockIdx.z;
    #pragma unroll
    for (int it = 0; it < 4; it++) {
        int l  = it*256 + tid;
        int tt = l >> 5, cc = l & 31;
        int t = t0 + tt, c = c0 + cc;
        int row = b*NT + t;
        float v = x[(size_t)row * NC + c];
        v = (v - g_mu[row]) * g_rstd[row] * gamma[c] + betaln[c];
        float am = fmaxf(__uint_as_float(g_absmax[b*NC + c]), 1e-5f);
        float q = rintf(v * (127.f / am));
        q = fminf(fmaxf(q, -127.f), 127.f);
        sq[cc*36 + tt] = (signed char)(int)q;
    }
    __syncthreads();
    int igl = tid >> 5, tt = tid & 31;
    int b0 = (int)sq[(igl*4+0)*36 + tt] & 0xFF;
    int b1 = (int)sq[(igl*4+1)*36 + tt] & 0xFF;
    int b2 = (int)sq[(igl*4+2)*36 + tt] & 0xFF;
    int b3 = (int)sq[(igl*4+3)*36 + tt] & 0xFF;
    int p = b0 | (b1 << 8) | (b2 << 16) | (b3 << 24);
    g_xq[((b*256) + (c0 >> 2) + igl) * XSTRIDE + 8 + t0 + tt] = p;
}

// ---------------- warp-specialized conv: 256-thread CTAs, 2/SM ----------------
// tile: 128 o x 128 t; warps 0-3 IMMA (cols 0..63), warps 4-7 dp4a (cols 64..127)

__device__ __forceinline__ void mma_s8(int& c0, int& c1, int& c2, int& c3,
                                       int a0, int a1, int a2, int a3,
                                       int b0, int b1) {
    asm volatile("mma.sync.aligned.m16n8k32.row.col.s32.s8.s8.s32 "
                 "{%0,%1,%2,%3}, {%4,%5,%6,%7}, {%8,%9}, {%0,%1,%2,%3};"
                 : "+r"(c0), "+r"(c1), "+r"(c2), "+r"(c3)
                 : "r"(a0), "r"(a1), "r"(a2), "r"(a3), "r"(b0), "r"(b1));
}
__device__ __forceinline__ void bulk_g2s(uint32_t dst, const void* src, uint32_t bytes, uint32_t mbar) {
    asm volatile("cp.async.bulk.shared::cta.global.mbarrier::complete_tx::bytes "
                 "[%0], [%1], %2, [%3];"
                 :: "r"(dst), "l"(src), "r"(bytes), "r"(mbar) : "memory");
}
__device__ __forceinline__ void mbar_init(uint32_t mbar, uint32_t count) {
    asm volatile("mbarrier.init.shared.b64 [%0], %1;" :: "r"(mbar), "r"(count) : "memory");
}
__device__ __forceinline__ void mbar_expect_tx(uint32_t mbar, uint32_t bytes) {
    asm volatile("mbarrier.arrive.expect_tx.shared.b64 _, [%0], %1;" :: "r"(mbar), "r"(bytes) : "memory");
}
__device__ __forceinline__ void mbar_wait(uint32_t mbar, uint32_t parity) {
    asm volatile("{\n\t"
                 ".reg .pred P;\n\t"
                 "WL_%=:\n\t"
                 "mbarrier.try_wait.parity.acquire.cta.shared::cta.b64 P, [%0], %1, 0x989680;\n\t"
                 "@P bra WD_%=;\n\t"
                 "bra WL_%=;\n\t"
                 "WD_%=:\n\t"
                 "}" :: "r"(mbar), "r"(parity) : "memory");
}

#define BSTRIDE 152                  // ints per B smem row (152 % 32 == 24, conflict-free)
#define BROWB   560                  // bytes per B row copy (140 ints: t0-8 .. t0+131)
#define CHUNK_TX (3*4096 + 8*BROWB)  // 16768
#define DPW 16                       // dp4a cols per lane group

__global__ void __launch_bounds__(256, 2)
k_conv_ws(float* __restrict__ out) {
    __shared__ __align__(16) int sA[2][3072];      // [buf][(k*128+row)*8 + j]  12KB each
    __shared__ __align__(16) int sB[2][8*BSTRIDE]; // [buf][ig*152 + col], col 0 == t0-8
    __shared__ __align__(8)  unsigned long long s_mbar[2];

    int tid  = threadIdx.x;
    int lane = tid & 31, warp = tid >> 5;
    int t0 = blockIdx.x * 128;
    int o0 = blockIdx.y * 128;
    int b  = blockIdx.z;

    const char* wqb = (const char*)g_wq;
    const int*  xq  = g_xq;

    uint32_t sA0 = (uint32_t)__cvta_generic_to_shared(&sA[0][0]);
    uint32_t sB0 = (uint32_t)__cvta_generic_to_shared(&sB[0][0]);
    uint32_t mb0 = (uint32_t)__cvta_generic_to_shared(&s_mbar[0]);
    uint32_t mb1 = (uint32_t)__cvta_generic_to_shared(&s_mbar[1]);

    if (tid == 0) { mbar_init(mb0, 1); mbar_init(mb1, 1); }
    __syncthreads();

    auto issue = [&](int ic, int buf) {
        uint32_t mb = buf ? mb1 : mb0;
        uint32_t dA = sA0 + buf*12288;
        uint32_t dB = sB0 + buf*(8*BSTRIDE*4);
        mbar_expect_tx(mb, CHUNK_TX);
        #pragma unroll
        for (int k = 0; k < 3; k++) {
            const void* src = wqb + ((size_t)((k*32 + ic)*NC + o0) << 5);
            bulk_g2s(dA + k*4096, src, 4096, mb);
        }
        #pragma unroll
        for (int ig = 0; ig < 8; ig++) {
            const void* src = xq + (size_t)(b*256 + ic*8 + ig) * XSTRIDE + t0;
            bulk_g2s(dB + ig*(BSTRIDE*4), src, BROWB, mb);
        }
    };

    // imma warps view acc as [mt][nt(8)][4]; dp4a warps as [s(4)][16]
    int acc[64];
    #pragma unroll
    for (int i = 0; i < 64; i++) acc[i] = 0;

    int q = lane & 3, r = lane >> 2;
    int wm = warp & 3;                 // imma warps 0..3: o = o0 + wm*32
    int w2m = (warp - 4) & 3;          // dp4a warps 4..7: o = o0 + w2m*32
    int ubase = q*DPW;                 // dp4a lane col base within 64-col region

    if (tid == 0) issue(0, 0);

    for (int ic = 0; ic < 32; ic++) {
        int buf = ic & 1;
        if (ic < 31 && tid == 0) issue(ic + 1, buf ^ 1);
        mbar_wait(buf ? mb1 : mb0, (ic >> 1) & 1);

        const int* A = sA[buf];
        const int* B = sB[buf];

        if (warp < 4) {
            // ---- IMMA: cols t0 .. t0+63 ----
            #pragma unroll
            for (int k = 0; k < 3; k++) {
                int a[2][4];
                #pragma unroll
                for (int mt = 0; mt < 2; mt++) {
                    int rb = wm*32 + mt*16;
                    const int* Ak = A + (k << 10);
                    a[mt][0] = Ak[((rb + r)     << 3) + q];
                    a[mt][1] = Ak[((rb + 8 + r) << 3) + q];
                    a[mt][2] = Ak[((rb + r)     << 3) + 4 + q];
                    a[mt][3] = Ak[((rb + 8 + r) << 3) + 4 + q];
                }
                #pragma unroll
                for (int nt = 0; nt < 8; nt++) {
                    int col = nt*8 + r + k + 7;   // sB col 0 == t0-8
                    int b0 = B[q*BSTRIDE + col];
                    int b1 = B[(4 + q)*BSTRIDE + col];
                    #pragma unroll
                    for (int mt = 0; mt < 2; mt++) {
                        int* ac = &acc[(mt*8 + nt)*4];
                        mma_s8(ac[0], ac[1], ac[2], ac[3],
                               a[mt][0], a[mt][1], a[mt][2], a[mt][3], b0, b1);
                    }
                }
            }
        } else {
            // ---- dp4a: cols t0+64 .. t0+127 ----
            #pragma unroll 1
            for (int j = 0; j < 8; j++) {
                int bb[24];
                #pragma unroll
                for (int i = 0; i < 6; i++) {
                    // base col 68+ubase is 16B-aligned (ubase multiple of 4); max col 139 < 140
                    int4 v = *(const int4*)&B[j*BSTRIDE + 68 + ubase + 4*i];
                    bb[4*i+0] = v.x; bb[4*i+1] = v.y; bb[4*i+2] = v.z; bb[4*i+3] = v.w;
                }
                int a[3][4];
                #pragma unroll
                for (int k = 0; k < 3; k++)
                    #pragma unroll
                    for (int s = 0; s < 4; s++)
                        a[k][s] = A[((k*128 + w2m*32 + s*8 + r) << 3) + j];
                // out t = t0+64+ubase+uu needs sB col = ubase+uu+k+71 -> bb[3+uu+k] (max 20 < 24)
                #pragma unroll
                for (int k = 0; k < 3; k++)
                    #pragma unroll
                    for (int s = 0; s < 4; s++)
                        #pragma unroll
                        for (int uu = 0; uu < DPW; uu++)
                            acc[s*DPW + uu] = __dp4a(a[k][s], bb[3 + uu + k], acc[s*DPW + uu]);
            }
        }
        __syncthreads();
    }

    // ---- epilogue ----
    float beta = fmaxf((float)(g_beta_acc * (1.0 / (double)NWELEM)), 1e-5f);
    if (warp < 4) {
        #pragma unroll
        for (int mt = 0; mt < 2; mt++) {
            int ro = o0 + wm*32 + mt*16 + r;
            float s0 = beta * fmaxf(__uint_as_float(g_absmax[b*NC + ro]),     1e-5f) * (1.f/127.f);
            float s1 = beta * fmaxf(__uint_as_float(g_absmax[b*NC + ro + 8]), 1e-5f) * (1.f/127.f);
            #pragma unroll
            for (int nt = 0; nt < 8; nt++) {
                int t = t0 + nt*8 + q*2;
                float* p0 = out + ((size_t)(b*NT + t)) * NC;
                float* p1 = p0 + NC;
                const int* ac = &acc[(mt*8 + nt)*4];
                p0[ro]     = (float)ac[0] * s0;
                p1[ro]     = (float)ac[1] * s0;
                p0[ro + 8] = (float)ac[2] * s1;
                p1[ro + 8] = (float)ac[3] * s1;
            }
        }
    } else {
        int tb = t0 + 64 + ubase;
        #pragma unroll
        for (int s = 0; s < 4; s++) {
            int ro = o0 + w2m*32 + s*8 + r;
            float osc = beta * fmaxf(__uint_as_float(g_absmax[b*NC + ro]), 1e-5f) * (1.f/127.f);
            #pragma unroll
            for (int uu = 0; uu < DPW; uu++) {
                int t = tb + uu;
                out[((size_t)(b*NT + t))*NC + ro] = (float)acc[s*DPW + uu] * osc;
            }
        }
    }
}

// ---------------- launch ----------------
extern "C" void kernel_launch(void* const* d_in, const int* in_sizes, int n_in,
                              void* d_out, int out_size) {
    const float* x      = (const float*)d_in[0];   // [8,4096,1024]
    const float* gamma  = (const float*)d_in[1];   // [1024]
    const float* betaln = (const float*)d_in[2];   // [1024]
    const float* W      = (const float*)d_in[3];   // [1024,1024,3]
    float* out = (float*)d_out;

    k_init<<<64, 256>>>();
    k_wsum<<<1536, 256>>>(W);
    k_quantw<<<(NK*NC*(NC/4) + 255)/256, 256>>>(W);
    k_stats<<<dim3(NT/32, NB), 256>>>(x, gamma, betaln);
    k_quantx<<<dim3(NT/32, NC/32, NB), 256>>>(x, gamma, betaln);
    k_conv_ws<<<dim3(NT/128, NC/128, NB), 256>>>(out);
}